// round 8
// baseline (speedup 1.0000x reference)
#include <cuda_runtime.h>
#include <cuda_bf16.h>
#include <math.h>
#include <stdint.h>

// Problem constants
#define NROWS   65536      // B*H*W
#define DDIM    256
#define KCODES  1024
#define GAMMA   0.9f
#define BETA    0.25f

// Output layout: ste[16777216], perplexity[1], loss[1], new_codebook[262144]
#define STE_OFF  0
#define PPL_OFF  16777216
#define LOSS_OFF 16777217
#define CB_OFF   16777218

// ---------------- scratch (device globals; no dynamic alloc allowed) ----------------
__device__ float g_cbT[KCODES * DDIM];              // codebook transposed [K][D] fp32
__device__ float g_norm[KCODES];                    // |e_k|^2
__device__ float g_dwT[KCODES * DDIM];              // dw transposed [K][D]
__device__ int   g_csi[KCODES];                     // cluster sizes (int)
__device__ float g_loss;                            // sum of squared residuals
__device__ float g_scs[KCODES];                     // smoothed cluster size
__device__ __nv_bfloat16 g_Bbf[KCODES * DDIM];      // codebook bf16 [K][D]
__device__ int   g_candi[NROWS * 8];                // candidate code indices
__device__ int   g_idx[NROWS];                      // chosen code per row
__device__ int   g_off[KCODES];                     // per-code list offset
__device__ int   g_cur[KCODES];                     // per-code scatter cursor
__device__ int   g_rows[NROWS];                     // rows sorted by code

// ---------------- PTX helpers (sm_80-class: valid on plain sm_103 target) ----------------
__device__ __forceinline__ uint32_t smem_u32(const void* p) {
    uint32_t a;
    asm("{ .reg .u64 t; cvta.to.shared.u64 t, %1; cvt.u32.u64 %0, t; }" : "=r"(a) : "l"(p));
    return a;
}
__device__ __forceinline__ void ldsm4(uint32_t* r, uint32_t addr) {
    asm volatile("ldmatrix.sync.aligned.m8n8.x4.shared.b16 {%0,%1,%2,%3}, [%4];"
        : "=r"(r[0]), "=r"(r[1]), "=r"(r[2]), "=r"(r[3]) : "r"(addr));
}
__device__ __forceinline__ void ldsm2(uint32_t* r, uint32_t addr) {
    asm volatile("ldmatrix.sync.aligned.m8n8.x2.shared.b16 {%0,%1}, [%2];"
        : "=r"(r[0]), "=r"(r[1]) : "r"(addr));
}
__device__ __forceinline__ void mma16816(float* c, const uint32_t* a, const uint32_t* b) {
    asm volatile(
        "mma.sync.aligned.m16n8k16.row.col.f32.bf16.bf16.f32 "
        "{%0,%1,%2,%3}, {%4,%5,%6,%7}, {%8,%9}, {%0,%1,%2,%3};"
        : "+f"(c[0]), "+f"(c[1]), "+f"(c[2]), "+f"(c[3])
        : "r"(a[0]), "r"(a[1]), "r"(a[2]), "r"(a[3]), "r"(b[0]), "r"(b[1]));
}
__device__ __forceinline__ void cpasync16(uint32_t s, const void* g) {
    asm volatile("cp.async.cg.shared.global [%0], [%1], 16;" :: "r"(s), "l"(g));
}
#define CP_COMMIT asm volatile("cp.async.commit_group;" ::: "memory")
#define CP_WAIT0  asm volatile("cp.async.wait_group 0;" ::: "memory")

// SMEM layout (bytes). A[64][264]bf16, B[2][128][136]bf16, norm[1024]f32
#define OFF_A     0
#define OFF_B     33792
#define BUFSZ     34816      // 128 * 136 * 2
#define OFF_NORM  103424
#define SMEM_BYTES 107520
#define LDA 264
#define LDB 136

// ---------------- kernel 0: zero scratch ----------------
__global__ void zero_k() {
    int i = blockIdx.x * blockDim.x + threadIdx.x;   // 1024 threads
    g_csi[i] = 0;
    if (i == 0) g_loss = 0.0f;
}

// ---------------- kernel 1: transpose codebook [D,K] -> [K,D] fp32 ----------------
__global__ void transpose_k(const float* __restrict__ cb) {
    __shared__ float tile[32][33];
    int kx = blockIdx.x * 32;
    int dy = blockIdx.y * 32;
    tile[threadIdx.y][threadIdx.x] = cb[(dy + threadIdx.y) * KCODES + kx + threadIdx.x];
    __syncthreads();
    g_cbT[(size_t)(kx + threadIdx.y) * DDIM + dy + threadIdx.x] = tile[threadIdx.x][threadIdx.y];
}

// ---------------- kernel 2: per-code squared norms + bf16 convert of codebook ----------------
__global__ void norm_conv_k() {
    int w = (blockIdx.x * blockDim.x + threadIdx.x) >> 5;
    int lane = threadIdx.x & 31;
    if (w >= KCODES) return;
    float s = 0.0f;
    #pragma unroll
    for (int j = 0; j < 8; j++) {
        int d = lane + j * 32;
        float v = g_cbT[(size_t)w * DDIM + d];
        g_Bbf[(size_t)w * DDIM + d] = __float2bfloat16_rn(v);
        s = fmaf(v, v, s);
    }
    #pragma unroll
    for (int off = 16; off > 0; off >>= 1)
        s += __shfl_xor_sync(0xffffffffu, s, off);
    if (lane == 0) g_norm[w] = s;
}

// ---------------- kernel 3: HMMA bf16 GEMM + fragment-resident top-2/quarter ----------------
// CTA: 64 rows x all 1024 codes. 8 warps (2 row-halves x 4 col-quarters), warp tile
// 32x32, mma m16n8k16. A loaded fp32 from x and converted to bf16 in-kernel.
// K-chunks of 128 (two per 128-code block). Per thread: running top-2 per owned
// fragment row; 4-lane shuffle merge gives top-2 per 256-code quarter -> 8 cands/row.
__global__ __launch_bounds__(256, 2) void gemm_hmma(const float* __restrict__ x) {
    extern __shared__ char smem[];
    __nv_bfloat16* As = (__nv_bfloat16*)(smem + OFF_A);
    float* s_norm = (float*)(smem + OFF_NORM);
    const uint32_t sA = smem_u32(smem + OFF_A);
    const uint32_t sB = smem_u32(smem + OFF_B);

    const int tid = threadIdx.x;
    const int lane = tid & 31;
    const int wid = tid >> 5;
    const int wm = wid >> 2;            // 0..1 (32-row half)
    const int wn = wid & 3;             // 0..3 (32-col quarter of each 128 block)
    const size_t row0 = (size_t)blockIdx.x * 64;

    // prefetch B chunk 0 early (overlaps A convert): 128 codes x 128 k
    #pragma unroll
    for (int j = 0; j < 8; j++) {
        int idx = tid + j * 256;        // 2048 uint4
        int n = idx >> 4, cv = idx & 15;
        cpasync16(sB + (n * LDB + cv * 8) * 2,
                  g_Bbf + (size_t)n * DDIM + cv * 8);
    }
    CP_COMMIT;

    // load norms
    for (int i = tid; i < KCODES; i += 256) s_norm[i] = g_norm[i];
    // load A tile 64x256 fp32 -> bf16 smem (padded)
    #pragma unroll
    for (int j = 0; j < 16; j++) {
        int idx = tid + j * 256;        // 4096 float4
        int r = idx >> 6, cv = idx & 63;
        float4 v = *(const float4*)(x + (row0 + r) * DDIM + cv * 4);
        union { __nv_bfloat16 h[4]; uint2 u; } o;
        o.h[0] = __float2bfloat16_rn(v.x); o.h[1] = __float2bfloat16_rn(v.y);
        o.h[2] = __float2bfloat16_rn(v.z); o.h[3] = __float2bfloat16_rn(v.w);
        *(uint2*)(As + r * LDA + cv * 4) = o.u;
    }

    // ldmatrix base addresses
    const uint32_t aBase = sA + (((wm * 32 + (lane & 15)) * LDA + 8 * (lane >> 4)) * 2);
    const uint32_t bBase = sB + (((wn * 32 + (lane & 7)) * LDB + 8 * ((lane >> 3) & 1)) * 2);

    float acc[2][4][4];
    // running top-2 per owned fragment row (4 rows per thread)
    float ts0[4], ts1[4];
    int   ti0[4], ti1[4];
    #pragma unroll
    for (int r = 0; r < 4; r++) {
        ts0[r] = -1e30f; ts1[r] = -1e30f; ti0[r] = 0; ti1[r] = 0;
    }

    for (int cidx = 0; cidx < 16; cidx++) {
        const int buf = cidx & 1, half = cidx & 1, bn = cidx >> 1;
        CP_WAIT0;
        __syncthreads();
        if (cidx < 15) {
            int c2 = cidx + 1, bn2 = c2 >> 1, half2 = c2 & 1, buf2 = c2 & 1;
            #pragma unroll
            for (int j = 0; j < 8; j++) {
                int idx = tid + j * 256;
                int n = idx >> 4, cv = idx & 15;
                cpasync16(sB + buf2 * BUFSZ + (n * LDB + cv * 8) * 2,
                          g_Bbf + (size_t)(bn2 * 128 + n) * DDIM + half2 * 128 + cv * 8);
            }
            CP_COMMIT;
        }
        if (half == 0) {
            #pragma unroll
            for (int mt = 0; mt < 2; mt++)
                #pragma unroll
                for (int nt = 0; nt < 4; nt++)
                    #pragma unroll
                    for (int e = 0; e < 4; e++) acc[mt][nt][e] = 0.0f;
        }
        // compute: 8 k16 steps over this 128-k chunk
        #pragma unroll
        for (int ks = 0; ks < 8; ks++) {
            uint32_t a[2][4], b[4][2];
            #pragma unroll
            for (int mt = 0; mt < 2; mt++)
                ldsm4(a[mt], aBase + (mt * 16 * LDA + half * 128 + ks * 16) * 2);
            #pragma unroll
            for (int nt = 0; nt < 4; nt++)
                ldsm2(b[nt], bBase + buf * BUFSZ + (nt * 8 * LDB + ks * 16) * 2);
            #pragma unroll
            for (int mt = 0; mt < 2; mt++)
                #pragma unroll
                for (int nt = 0; nt < 4; nt++)
                    mma16816(acc[mt][nt], a[mt], b[nt]);
        }
        if (half == 1) {
            // fold this block's scores into per-row running top-2
            const int cbase = bn * 128 + wn * 32 + 2 * (lane & 3);
            #pragma unroll
            for (int mt = 0; mt < 2; mt++)
                #pragma unroll
                for (int e = 0; e < 4; e++) {
                    const int rr = mt * 2 + (e >> 1);
                    #pragma unroll
                    for (int nt = 0; nt < 4; nt++) {
                        int code = cbase + nt * 8 + (e & 1);
                        float s = fmaf(2.0f, acc[mt][nt][e], -s_norm[code]);
                        if (s > ts1[rr]) {
                            if (s > ts0[rr]) {
                                ts1[rr] = ts0[rr]; ti1[rr] = ti0[rr];
                                ts0[rr] = s;       ti0[rr] = code;
                            } else {
                                ts1[rr] = s;       ti1[rr] = code;
                            }
                        }
                    }
                }
        }
    }

    // merge top-2 across the 4 lanes sharing each row (lane groups of 4)
    #pragma unroll
    for (int rr = 0; rr < 4; rr++) {
        #pragma unroll
        for (int off = 1; off < 4; off <<= 1) {
            float o0 = __shfl_xor_sync(0xffffffffu, ts0[rr], off, 4);
            int   oi0 = __shfl_xor_sync(0xffffffffu, ti0[rr], off, 4);
            float o1 = __shfl_xor_sync(0xffffffffu, ts1[rr], off, 4);
            int   oi1 = __shfl_xor_sync(0xffffffffu, ti1[rr], off, 4);
            if (o0 > ts0[rr]) {
                if (o1 > ts0[rr]) { ts1[rr] = o1;      ti1[rr] = oi1; }
                else              { ts1[rr] = ts0[rr]; ti1[rr] = ti0[rr]; }
                ts0[rr] = o0; ti0[rr] = oi0;
            } else if (o0 > ts1[rr]) {
                ts1[rr] = o0; ti1[rr] = oi0;
            }
        }
    }
    if ((lane & 3) == 0) {
        const int g = lane >> 2;
        #pragma unroll
        for (int rr = 0; rr < 4; rr++) {
            int row = wm * 32 + (rr >> 1) * 16 + (rr & 1) * 8 + g;
            g_candi[(row0 + row) * 8 + wn * 2 + 0] = ti0[rr];
            g_candi[(row0 + row) * 8 + wn * 2 + 1] = ti1[rr];
        }
    }
}

// ---------------- kernel 4: exact rescore (R1-identical arithmetic) + ste/loss/idx ----------
// 4 rows per warp; each 8-lane group owns one row; each lane rescans one candidate
// with the sequential fp32 FMA chain over k=0..255 (bit-identical to R1 scoring),
// group argmax with ties -> lowest index. No dw atomics (sort-gather phase follows).
__global__ void assign_k(const float* __restrict__ flat, float* __restrict__ out) {
    __shared__ float sloss[32];
    const int lane = threadIdx.x & 31;
    const int g = lane >> 3, sub = lane & 7;
    const int gw = (blockIdx.x * blockDim.x + threadIdx.x) >> 5;
    const int row = gw * 4 + g;

    const float* x = flat + (size_t)row * DDIM;

    int cand = g_candi[row * 8 + sub];
    const float4* e4 = (const float4*)(g_cbT + (size_t)cand * DDIM);
    const float4* x4 = (const float4*)x;
    float d = 0.0f;
    #pragma unroll 8
    for (int kb = 0; kb < 64; kb++) {
        float4 ev = e4[kb];
        float4 xv = x4[kb];
        d = fmaf(xv.x, ev.x, d);
        d = fmaf(xv.y, ev.y, d);
        d = fmaf(xv.z, ev.z, d);
        d = fmaf(xv.w, ev.w, d);
    }
    float s = fmaf(2.0f, d, -g_norm[cand]);
    // argmax within each 8-lane group, tie -> lower index
    #pragma unroll
    for (int off = 4; off > 0; off >>= 1) {
        float so = __shfl_xor_sync(0xffffffffu, s, off, 8);
        int   co = __shfl_xor_sync(0xffffffffu, cand, off, 8);
        if (so > s || (so == s && co < cand)) { s = so; cand = co; }
    }
    int bk = __shfl_sync(0xffffffffu, cand, lane & 24);

    const float* q = g_cbT + (size_t)bk * DDIM;
    float* ste = out + STE_OFF + (size_t)row * DDIM;
    float sum = 0.0f;
    #pragma unroll
    for (int j = 0; j < 8; j++) {
        float4 xv = *(const float4*)(x + j * 32 + sub * 4);
        float4 qv = *(const float4*)(q + j * 32 + sub * 4);
        float4 dv = make_float4(qv.x - xv.x, qv.y - xv.y, qv.z - xv.z, qv.w - xv.w);
        float4 sv = make_float4(xv.x + dv.x, xv.y + dv.y, xv.z + dv.z, xv.w + dv.w);
        *(float4*)(ste + j * 32 + sub * 4) = sv;
        sum = fmaf(dv.x, dv.x, sum);
        sum = fmaf(dv.y, dv.y, sum);
        sum = fmaf(dv.z, dv.z, sum);
        sum = fmaf(dv.w, dv.w, sum);
    }
    #pragma unroll
    for (int off = 4; off > 0; off >>= 1)
        sum += __shfl_xor_sync(0xffffffffu, sum, off, 8);
    if (sub == 0) {
        g_idx[row] = bk;
        atomicAdd(&g_csi[bk], 1);
        sloss[(threadIdx.x >> 5) * 4 + g] = sum;
    }
    __syncthreads();
    if (threadIdx.x == 0) {
        float tot = 0.0f;
        #pragma unroll
        for (int i = 0; i < 32; i++) tot += sloss[i];
        atomicAdd(&g_loss, tot);
    }
}

// ---------------- kernel 5: exclusive prefix sum of cluster sizes ----------------
__global__ void prefix_k() {
    __shared__ int tmp[1024];
    int t = threadIdx.x;
    int v = g_csi[t];
    tmp[t] = v;
    __syncthreads();
    #pragma unroll
    for (int off = 1; off < 1024; off <<= 1) {
        int o = (t >= off) ? tmp[t - off] : 0;
        __syncthreads();
        tmp[t] += o;
        __syncthreads();
    }
    int excl = tmp[t] - v;
    g_off[t] = excl;
    g_cur[t] = excl;
}

// ---------------- kernel 6: scatter rows into per-code lists ----------------
__global__ void scatter_k() {
    int i = blockIdx.x * blockDim.x + threadIdx.x;
    int k = g_idx[i];
    int pos = atomicAdd(&g_cur[k], 1);
    g_rows[pos] = i;
}

// ---------------- kernel 7: dw accumulation, one CTA per code, no atomics ----------------
__global__ void dw_k(const float* __restrict__ x) {
    const int k = blockIdx.x, t = threadIdx.x;
    const int off = g_off[k], cnt = g_csi[k];
    float acc = 0.0f;
    int j = 0;
    for (; j + 4 <= cnt; j += 4) {
        int r0 = g_rows[off + j + 0];
        int r1 = g_rows[off + j + 1];
        int r2 = g_rows[off + j + 2];
        int r3 = g_rows[off + j + 3];
        float v0 = x[(size_t)r0 * DDIM + t];
        float v1 = x[(size_t)r1 * DDIM + t];
        float v2 = x[(size_t)r2 * DDIM + t];
        float v3 = x[(size_t)r3 * DDIM + t];
        acc += v0; acc += v1; acc += v2; acc += v3;
    }
    for (; j < cnt; j++)
        acc += x[(size_t)g_rows[off + j] * DDIM + t];
    g_dwT[(size_t)k * DDIM + t] = acc;
}

// ---------------- kernel 8: cluster-size smoothing, perplexity, loss ----------------
__global__ void finalA(const float* __restrict__ ehc, const int* __restrict__ counter,
                       float* __restrict__ out) {
    __shared__ float red[1024];
    int k = threadIdx.x;
    float bias = 1.0f - powf(GAMMA, (float)(*counter));
    float cs = (float)g_csi[k];
    float avg = (ehc[k] * GAMMA + cs * (1.0f - GAMMA)) / bias;

    red[k] = avg;
    __syncthreads();
    for (int st = 512; st > 0; st >>= 1) {
        if (k < st) red[k] += red[k + st];
        __syncthreads();
    }
    float n = red[0];
    __syncthreads();

    g_scs[k] = (avg + 1e-5f) / (n + (float)KCODES * 1e-5f) * n;

    float p = cs * (1.0f / (float)NROWS);
    red[k] = -p * logf(p + 1e-10f);
    __syncthreads();
    for (int st = 512; st > 0; st >>= 1) {
        if (k < st) red[k] += red[k + st];
        __syncthreads();
    }
    if (k == 0) {
        out[PPL_OFF]  = expf(red[0]);
        out[LOSS_OFF] = BETA * g_loss / (float)((size_t)NROWS * DDIM);
    }
}

// ---------------- kernel 9: new codebook ----------------
__global__ void finalB(const float* __restrict__ edw, const int* __restrict__ counter,
                       float* __restrict__ out) {
    int i = blockIdx.x * blockDim.x + threadIdx.x;   // d*K + k
    int d = i >> 10;
    int k = i & 1023;
    float bias = 1.0f - powf(GAMMA, (float)(*counter));
    float hdw = edw[i] * GAMMA + g_dwT[(size_t)k * DDIM + d] * (1.0f - GAMMA);
    out[CB_OFF + i] = (hdw / bias) / g_scs[k];
}

// ---------------- launch ----------------
extern "C" void kernel_launch(void* const* d_in, const int* in_sizes, int n_in,
                              void* d_out, int out_size) {
    const float* x   = (const float*)d_in[0];   // inputs [B,H,W,D]
    const float* cb  = (const float*)d_in[1];   // codebook [D,K]
    const float* ehc = (const float*)d_in[2];   // ema_hidden_cluster [K]
    const float* edw = (const float*)d_in[3];   // ema_hidden_dw [D,K]
    const int* counter = (const int*)d_in[4];
    float* out = (float*)d_out;

    static int attr_done = 0;
    if (!attr_done) {
        cudaFuncSetAttribute(gemm_hmma, cudaFuncAttributeMaxDynamicSharedMemorySize,
                             SMEM_BYTES);
        attr_done = 1;
    }

    zero_k<<<4, 256>>>();
    transpose_k<<<dim3(KCODES / 32, DDIM / 32), dim3(32, 32)>>>(cb);
    norm_conv_k<<<KCODES * 32 / 256, 256>>>();
    gemm_hmma<<<NROWS / 64, 256, SMEM_BYTES>>>(x);
    assign_k<<<NROWS / 32, 256>>>(x, out);
    prefix_k<<<1, 1024>>>();
    scatter_k<<<NROWS / 256, 256>>>();
    dw_k<<<KCODES, 256>>>(x);
    finalA<<<1, 1024>>>(ehc, counter, out);
    finalB<<<KCODES * DDIM / 256, 256>>>(edw, counter, out);
}